// round 1
// baseline (speedup 1.0000x reference)
#include <cuda_runtime.h>
#include <math.h>

// Problem constants
#define NB     2
#define SEQ    2048
#define EMB    1024
#define NHEADS 16
#define HD     64
#define MROWS  (NB * SEQ)   // 4096

// Scratch for projected q/k/v: [MROWS, EMB] each (fp32). Static device globals
// (allocation inside kernel_launch is forbidden).
__device__ float g_q[MROWS * EMB];
__device__ float g_k[MROWS * EMB];
__device__ float g_v[MROWS * EMB];

// ---------------------------------------------------------------------------
// Projection GEMM (NT): C[i][j] = sum_k A[i][k] * W[j][k]
// A: [4096,1024] row-major, W: [1024,1024] row-major, C: [4096,1024]
// blockIdx.z selects which of the three projections to compute.
// Tile 128x128x16, 256 threads, 8x8 per thread.
// ---------------------------------------------------------------------------
#define BM   128
#define BN   128
#define BKG  16
#define GPAD 4

__global__ __launch_bounds__(256) void proj_gemm(
    const float* __restrict__ Av, const float* __restrict__ Ak,
    const float* __restrict__ Aq,
    const float* __restrict__ Wv, const float* __restrict__ Wk,
    const float* __restrict__ Wq)
{
    const float* A;
    const float* W;
    float* C;
    if (blockIdx.z == 0)      { A = Av; W = Wv; C = g_v; }
    else if (blockIdx.z == 1) { A = Ak; W = Wk; C = g_k; }
    else                      { A = Aq; W = Wq; C = g_q; }

    __shared__ float As[BKG][BM + GPAD];  // transposed: As[k][m]
    __shared__ float Bs[BKG][BN + GPAD];  // transposed: Bs[k][n]

    const int tid = threadIdx.x;
    const int tx  = tid & 15;
    const int ty  = tid >> 4;
    const int m0  = blockIdx.y * BM;
    const int n0  = blockIdx.x * BN;

    float acc[8][8];
#pragma unroll
    for (int i = 0; i < 8; i++)
#pragma unroll
        for (int j = 0; j < 8; j++) acc[i][j] = 0.f;

    for (int k0 = 0; k0 < EMB; k0 += BKG) {
        // A tile: 128 rows x 16 k = 512 float4; 2 per thread, coalesced.
#pragma unroll
        for (int it = 0; it < 2; it++) {
            int f   = tid + 256 * it;        // 0..511
            int row = f >> 2;                // 0..127
            int kp  = (f & 3) * 4;           // 0,4,8,12
            float4 v = *(const float4*)&A[(size_t)(m0 + row) * EMB + k0 + kp];
            As[kp + 0][row] = v.x;
            As[kp + 1][row] = v.y;
            As[kp + 2][row] = v.z;
            As[kp + 3][row] = v.w;
        }
#pragma unroll
        for (int it = 0; it < 2; it++) {
            int f   = tid + 256 * it;
            int row = f >> 2;
            int kp  = (f & 3) * 4;
            float4 v = *(const float4*)&W[(size_t)(n0 + row) * EMB + k0 + kp];
            Bs[kp + 0][row] = v.x;
            Bs[kp + 1][row] = v.y;
            Bs[kp + 2][row] = v.z;
            Bs[kp + 3][row] = v.w;
        }
        __syncthreads();

#pragma unroll
        for (int k = 0; k < BKG; k++) {
            float a[8], b[8];
            *(float4*)&a[0] = *(const float4*)&As[k][8 * ty];
            *(float4*)&a[4] = *(const float4*)&As[k][8 * ty + 4];
            *(float4*)&b[0] = *(const float4*)&Bs[k][8 * tx];
            *(float4*)&b[4] = *(const float4*)&Bs[k][8 * tx + 4];
#pragma unroll
            for (int i = 0; i < 8; i++)
#pragma unroll
                for (int j = 0; j < 8; j++) acc[i][j] += a[i] * b[j];
        }
        __syncthreads();
    }

#pragma unroll
    for (int i = 0; i < 8; i++) {
        float* crow = &C[(size_t)(m0 + 8 * ty + i) * EMB + n0 + 8 * tx];
        *(float4*)&crow[0] = *(float4*)&acc[i][0];
        *(float4*)&crow[4] = *(float4*)&acc[i][4];
    }
}

// ---------------------------------------------------------------------------
// Flash attention (fp32, online softmax).
// Grid: (SEQ/64, NHEADS, NB). 256 threads. Q-tile 64, KV-tile 64, D=64.
// Thread (ty,tx) in 16x16 grid owns a 4x4 microtile: rows 4ty.., cols 4tx..
// smem (dynamic, 69632 B):
//   Qs[d][q]  64x68   (Q pre-scaled by 1/sqrt(D))
//   Ks[d][k]  64x68
//   Vs[k][d]  64x68
//   Ps[k][q]  64x68   (transposed probabilities for the PV matmul)
// ---------------------------------------------------------------------------
#define BQ   64
#define BKV  64
#define APAD 4
#define AROW (BQ + APAD)   // 68

__global__ __launch_bounds__(256) void attn_kernel(float* __restrict__ out)
{
    extern __shared__ float smem[];
    float (*Qs)[AROW] = (float (*)[AROW])(smem);
    float (*Ks)[AROW] = (float (*)[AROW])(smem + 64 * AROW);
    float (*Vs)[AROW] = (float (*)[AROW])(smem + 2 * 64 * AROW);
    float (*Ps)[AROW] = (float (*)[AROW])(smem + 3 * 64 * AROW);

    const int tid = threadIdx.x;
    const int tx  = tid & 15;
    const int ty  = tid >> 4;
    const int qb  = blockIdx.x;
    const int h   = blockIdx.y;
    const int n   = blockIdx.z;

    const float scale = 0.125f;  // 1/sqrt(64)

    const float* qbase = g_q + ((size_t)(n * SEQ + qb * BQ)) * EMB + h * HD;
    const float* kroot = g_k + ((size_t)(n * SEQ)) * EMB + h * HD;
    const float* vroot = g_v + ((size_t)(n * SEQ)) * EMB + h * HD;

    // Load Q tile (transposed, pre-scaled). 1024 float4, 4 per thread.
#pragma unroll
    for (int it = 0; it < 4; it++) {
        int f   = tid + 256 * it;
        int row = f >> 4;            // query row 0..63
        int d0  = (f & 15) * 4;      // head-dim 0..60
        float4 v = *(const float4*)&qbase[(size_t)row * EMB + d0];
        Qs[d0 + 0][row] = v.x * scale;
        Qs[d0 + 1][row] = v.y * scale;
        Qs[d0 + 2][row] = v.z * scale;
        Qs[d0 + 3][row] = v.w * scale;
    }

    float acc[4][4];
    float m[4], l[4];
#pragma unroll
    for (int a = 0; a < 4; a++) {
        m[a] = -INFINITY;
        l[a] = 0.f;
#pragma unroll
        for (int b = 0; b < 4; b++) acc[a][b] = 0.f;
    }
    __syncthreads();  // Qs ready

    for (int t = 0; t < SEQ / BKV; t++) {
        const float* kbase = kroot + (size_t)(t * BKV) * EMB;
        const float* vbase = vroot + (size_t)(t * BKV) * EMB;

        // K tile transposed, V tile natural. 4 float4 each per thread.
#pragma unroll
        for (int it = 0; it < 4; it++) {
            int f   = tid + 256 * it;
            int row = f >> 4;
            int d0  = (f & 15) * 4;
            float4 v = *(const float4*)&kbase[(size_t)row * EMB + d0];
            Ks[d0 + 0][row] = v.x;
            Ks[d0 + 1][row] = v.y;
            Ks[d0 + 2][row] = v.z;
            Ks[d0 + 3][row] = v.w;
        }
#pragma unroll
        for (int it = 0; it < 4; it++) {
            int f   = tid + 256 * it;
            int row = f >> 4;
            int d0  = (f & 15) * 4;
            float4 v = *(const float4*)&vbase[(size_t)row * EMB + d0];
            *(float4*)&Vs[row][d0] = v;
        }
        __syncthreads();  // K/V ready

        // S = (Q*scale) K^T : 4x4 per thread
        float s[4][4];
#pragma unroll
        for (int a = 0; a < 4; a++)
#pragma unroll
            for (int b = 0; b < 4; b++) s[a][b] = 0.f;

#pragma unroll 8
        for (int d = 0; d < HD; d++) {
            float4 qv = *(const float4*)&Qs[d][4 * ty];
            float4 kv = *(const float4*)&Ks[d][4 * tx];
            float qa[4] = {qv.x, qv.y, qv.z, qv.w};
            float kb[4] = {kv.x, kv.y, kv.z, kv.w};
#pragma unroll
            for (int a = 0; a < 4; a++)
#pragma unroll
                for (int b = 0; b < 4; b++) s[a][b] += qa[a] * kb[b];
        }

        // Online softmax per query row (rows shared across the 16 tx lanes).
#pragma unroll
        for (int a = 0; a < 4; a++) {
            float rmax = fmaxf(fmaxf(s[a][0], s[a][1]), fmaxf(s[a][2], s[a][3]));
#pragma unroll
            for (int off = 8; off >= 1; off >>= 1)
                rmax = fmaxf(rmax, __shfl_xor_sync(0xffffffffu, rmax, off));

            float mnew = fmaxf(m[a], rmax);
            float corr = __expf(m[a] - mnew);

            float rsum = 0.f;
#pragma unroll
            for (int b = 0; b < 4; b++) {
                float p = __expf(s[a][b] - mnew);
                s[a][b] = p;
                rsum += p;
            }
#pragma unroll
            for (int off = 8; off >= 1; off >>= 1)
                rsum += __shfl_xor_sync(0xffffffffu, rsum, off);

            l[a] = l[a] * corr + rsum;
            m[a] = mnew;
#pragma unroll
            for (int b = 0; b < 4; b++) acc[a][b] *= corr;
        }

        // Write P transposed: Ps[key][query]
#pragma unroll
        for (int b = 0; b < 4; b++) {
            float4 pw = make_float4(s[0][b], s[1][b], s[2][b], s[3][b]);
            *(float4*)&Ps[4 * tx + b][4 * ty] = pw;
        }
        __syncthreads();  // Ps ready

        // O += P V
#pragma unroll 8
        for (int k = 0; k < BKV; k++) {
            float4 pv = *(const float4*)&Ps[k][4 * ty];
            float4 vv = *(const float4*)&Vs[k][4 * tx];
            float pa[4] = {pv.x, pv.y, pv.z, pv.w};
            float vb[4] = {vv.x, vv.y, vv.z, vv.w};
#pragma unroll
            for (int a = 0; a < 4; a++)
#pragma unroll
                for (int b = 0; b < 4; b++) acc[a][b] += pa[a] * vb[b];
        }
        __syncthreads();  // all smem consumers done before next tile's loads
    }

    // Epilogue: out[n, q, h*64 + d] = acc / l
#pragma unroll
    for (int a = 0; a < 4; a++) {
        float inv_l = 1.f / l[a];
        int qrow = qb * BQ + 4 * ty + a;
        float4 o = make_float4(acc[a][0] * inv_l, acc[a][1] * inv_l,
                               acc[a][2] * inv_l, acc[a][3] * inv_l);
        *(float4*)&out[((size_t)(n * SEQ + qrow)) * EMB + h * HD + 4 * tx] = o;
    }
}

// ---------------------------------------------------------------------------
extern "C" void kernel_launch(void* const* d_in, const int* in_sizes, int n_in,
                              void* d_out, int out_size)
{
    (void)in_sizes; (void)n_in; (void)out_size;
    const float* values  = (const float*)d_in[0];
    const float* keys    = (const float*)d_in[1];
    const float* queries = (const float*)d_in[2];
    const float* Wv      = (const float*)d_in[3];
    const float* Wk      = (const float*)d_in[4];
    const float* Wq      = (const float*)d_in[5];
    float* out = (float*)d_out;

    // Projections: grid (N/BN, M/BM, 3)
    dim3 ggrid(EMB / BN, MROWS / BM, 3);
    proj_gemm<<<ggrid, 256>>>(values, keys, queries, Wv, Wk, Wq);

    // Attention
    const int smem_bytes = 4 * 64 * AROW * (int)sizeof(float);  // 69632
    cudaFuncSetAttribute(attn_kernel,
                         cudaFuncAttributeMaxDynamicSharedMemorySize, smem_bytes);
    dim3 agrid(SEQ / BQ, NHEADS, NB);
    attn_kernel<<<agrid, 256, smem_bytes>>>(out);
}